// round 10
// baseline (speedup 1.0000x reference)
#include <cuda_runtime.h>
#include <cstdint>

// Problem dimensions (fixed per reference)
#define ED 1024           // embedding dim D
#define NH 4              // heads
#define NB 4              // batch
#define SL 2048           // sequence length
#define MT (NB*SL)        // total tokens = 8192

// ---------------- scratch (static device globals; no allocation) -------------
__device__ float g_q[(size_t)NH*NB*SL*ED];
__device__ float g_k[(size_t)NH*NB*SL*ED];
__device__ float g_v[(size_t)NH*NB*SL*ED];
__device__ float g_scores[(size_t)NH*NB*SL*SL];
__device__ float g_heads[(size_t)NH*NB*SL*ED];
__device__ float g_proj[(size_t)MT*ED];
__device__ float g_y[(size_t)MT*ED];
__device__ float g_t[(size_t)MT*ED];

// ---------------------------------------------------------------------------
__device__ __forceinline__ void mma_tf32(float* acc, const uint32_t* a, const uint32_t* b)
{
    asm volatile(
        "mma.sync.aligned.m16n8k8.row.col.f32.tf32.tf32.f32 "
        "{%0,%1,%2,%3}, {%4,%5,%6,%7}, {%8,%9}, {%0,%1,%2,%3};"
        : "+f"(acc[0]), "+f"(acc[1]), "+f"(acc[2]), "+f"(acc[3])
        : "r"(a[0]), "r"(a[1]), "r"(a[2]), "r"(a[3]), "r"(b[0]), "r"(b[1]));
}

__device__ __forceinline__ void cp_async16(uint32_t dst, const void* src)
{
    asm volatile("cp.async.cg.shared.global [%0], [%1], 16;" :: "r"(dst), "l"(src));
}

// smem geometry (uint32 words per stage)
#define A_STRIDE 20                    // 16 k-words + pad 4  (conflict-free)
#define BN_STRIDE 264                  // 256 + 8
#define A_WORDS   (128 * A_STRIDE)     // 2560
#define B_WORDS   (256 * A_STRIDE)     // 5120 (>= 16*264=4224, covers both layouts)
#define STAGE_WORDS (A_WORDS + B_WORDS)     // 7680
#define STAGE_BYTES (STAGE_WORDS * 4)       // 30720
#define NSTAGE 4
#define SMEM_BYTES  (NSTAGE * STAGE_BYTES)  // 122880

// ---------------------------------------------------------------------------
// TF32 tensor-core GEMM, 4-stage cp.async pipeline, one barrier per k-iter.
// Block tile 128(M) x 256(N), BK=16, 256 threads = 8 warps, warp tile 64x64
// (2 M-warps x 4 N-warps), each warp = 4x8 grid of m16n8k8 mma tiles.
// Smem layouts (gmem-native, no transpose, no conversion):
//   A  : [128 rows][20]  row-major m x k
//   B^T: [256 rows][20]  row-major n x k        (TRANSB)
//   B  : [16 rows][264]  row-major k x n        (NN)
// fp32 bits fed directly to tf32 MMA (HW truncation).
// Optional bias[N] (offset z*sBiasz), optional accumulate. Batched over z.
// Requires M % 128 == 0, N % 256 == 0, K % 16 == 0.
// ---------------------------------------------------------------------------
template <bool TRANSB>
__global__ __launch_bounds__(256) void gemm_tf32_kernel(
    const float* __restrict__ A, const float* __restrict__ Bm,
    const float* __restrict__ bias, float* __restrict__ C,
    int M, int N, int K,
    long sAz, long sBz, long sCz, long sBiasz,
    float alpha, int accumulate)
{
    extern __shared__ uint32_t smem[];

    A  += (long)blockIdx.z * sAz;
    Bm += (long)blockIdx.z * sBz;
    C  += (long)blockIdx.z * sCz;
    if (bias) bias += (long)blockIdx.z * sBiasz;

    const int tid  = threadIdx.x;
    const int lane = tid & 31;
    const int warp = tid >> 5;
    const int g    = lane >> 2;   // 0..7
    const int t    = lane & 3;    // 0..3

    const int m0 = blockIdx.y * 128;
    const int n0 = blockIdx.x * 256;
    const int wm = (warp >> 2) * 64;   // M offset (0 or 64)
    const int wn = (warp & 3) * 64;    // N offset (0,64,128,192)

    const uint32_t smem_u32 = (uint32_t)__cvta_generic_to_shared(smem);

    float acc[4][8][4];
    #pragma unroll
    for (int mi = 0; mi < 4; mi++)
        #pragma unroll
        for (int ni = 0; ni < 8; ni++)
            #pragma unroll
            for (int r = 0; r < 4; r++) acc[mi][ni][r] = 0.f;

    const int KT = K >> 4;

    // ---- issue async copies for tile kt (guarded); ALWAYS commits a group
    auto issue = [&](int kt) {
        if (kt < KT) {
            const int k0 = kt << 4;
            const int stage = kt & (NSTAGE - 1);
            const uint32_t Sa = smem_u32 + stage * STAGE_BYTES;
            const uint32_t Sb = Sa + A_WORDS * 4;
            #pragma unroll
            for (int p = 0; p < 2; p++) {             // A: 512 16B chunks
                const int c = tid + p * 256, row = c >> 2, ch = c & 3;
                cp_async16(Sa + (row * A_STRIDE + ch * 4) * 4,
                           A + (long)(m0 + row) * K + k0 + ch * 4);
            }
            if (TRANSB) {
                #pragma unroll
                for (int p = 0; p < 4; p++) {         // B^T: 1024 chunks
                    const int c = tid + p * 256, row = c >> 2, ch = c & 3;
                    cp_async16(Sb + (row * A_STRIDE + ch * 4) * 4,
                               Bm + (long)(n0 + row) * K + k0 + ch * 4);
                }
            } else {
                #pragma unroll
                for (int p = 0; p < 4; p++) {         // B: 16 x 64 chunks
                    const int c = tid + p * 256, kr = c >> 6, ch = c & 63;
                    cp_async16(Sb + (kr * BN_STRIDE + ch * 4) * 4,
                               Bm + (long)(k0 + kr) * N + n0 + ch * 4);
                }
            }
        }
        asm volatile("cp.async.commit_group;");
    };

    // prologue: 3 tiles in flight
    issue(0); issue(1); issue(2);

    for (int kt = 0; kt < KT; kt++) {
        // retire until stage kt is resident (<=2 groups pending)
        asm volatile("cp.async.wait_group 2;");
        __syncthreads();      // also protects stage (kt+3)&3 from WAR below

        issue(kt + 3);

        const uint32_t* Sa = smem + (kt & (NSTAGE - 1)) * STAGE_WORDS;
        const uint32_t* Sb = Sa + A_WORDS;

        #pragma unroll
        for (int kk = 0; kk < 16; kk += 8) {
            uint32_t af[4][4], bf[8][2];
            #pragma unroll
            for (int mi = 0; mi < 4; mi++) {
                const int rb = (wm + mi * 16 + g) * A_STRIDE + kk + t;
                af[mi][0] = Sa[rb];
                af[mi][1] = Sa[rb + 8 * A_STRIDE];
                af[mi][2] = Sa[rb + 4];
                af[mi][3] = Sa[rb + 8 * A_STRIDE + 4];
            }
            if (TRANSB) {
                #pragma unroll
                for (int ni = 0; ni < 8; ni++) {
                    const int rb = (wn + ni * 8 + g) * A_STRIDE + kk + t;
                    bf[ni][0] = Sb[rb];
                    bf[ni][1] = Sb[rb + 4];
                }
            } else {
                #pragma unroll
                for (int ni = 0; ni < 8; ni++) {
                    const int nc = wn + ni * 8 + g;
                    bf[ni][0] = Sb[(kk + t) * BN_STRIDE + nc];
                    bf[ni][1] = Sb[(kk + t + 4) * BN_STRIDE + nc];
                }
            }
            #pragma unroll
            for (int mi = 0; mi < 4; mi++)
                #pragma unroll
                for (int ni = 0; ni < 8; ni++)
                    mma_tf32(acc[mi][ni], af[mi], bf[ni]);
        }
    }

    // ---- epilogue (c0/c1 -> row g, c2/c3 -> row g+8; cols 2t, 2t+1)
    #pragma unroll
    for (int mi = 0; mi < 4; mi++) {
        #pragma unroll
        for (int ni = 0; ni < 8; ni++) {
            const int col = n0 + wn + ni * 8 + 2 * t;
            #pragma unroll
            for (int h = 0; h < 2; h++) {
                const int row = m0 + wm + mi * 16 + g + h * 8;
                float2 r;
                r.x = acc[mi][ni][h * 2 + 0] * alpha;
                r.y = acc[mi][ni][h * 2 + 1] * alpha;
                if (bias) {
                    r.x += bias[col];
                    r.y += bias[col + 1];
                }
                float* cp = C + (long)row * N + col;
                if (accumulate) {
                    float2 o = *(const float2*)cp;
                    r.x += o.x; r.y += o.y;
                }
                *(float2*)cp = r;
            }
        }
    }
}

// ---------------------------------------------------------------------------
// Single-pass row softmax over SL=2048, in place. 256 threads, 8 vals/thread.
// ---------------------------------------------------------------------------
__global__ __launch_bounds__(256) void softmax_kernel(float* __restrict__ sc)
{
    float4* p4 = (float4*)(sc + (long)blockIdx.x * SL);
    const int tid = threadIdx.x;
    const int lane = tid & 31;
    const int warp = tid >> 5;
    __shared__ float red[8];

    float4 v0 = p4[tid];
    float4 v1 = p4[tid + 256];

    float m = fmaxf(fmaxf(fmaxf(v0.x, v0.y), fmaxf(v0.z, v0.w)),
                    fmaxf(fmaxf(v1.x, v1.y), fmaxf(v1.z, v1.w)));
    #pragma unroll
    for (int s = 16; s > 0; s >>= 1) m = fmaxf(m, __shfl_xor_sync(0xffffffffu, m, s));
    if (lane == 0) red[warp] = m;
    __syncthreads();
    if (warp == 0) {
        float mm = red[lane & 7];
        #pragma unroll
        for (int s = 4; s > 0; s >>= 1) mm = fmaxf(mm, __shfl_xor_sync(0xffffffffu, mm, s));
        if (lane == 0) red[0] = mm;
    }
    __syncthreads();
    const float mv = red[0];
    __syncthreads();

    v0.x = __expf(v0.x - mv); v0.y = __expf(v0.y - mv);
    v0.z = __expf(v0.z - mv); v0.w = __expf(v0.w - mv);
    v1.x = __expf(v1.x - mv); v1.y = __expf(v1.y - mv);
    v1.z = __expf(v1.z - mv); v1.w = __expf(v1.w - mv);
    float s = v0.x + v0.y + v0.z + v0.w + v1.x + v1.y + v1.z + v1.w;
    #pragma unroll
    for (int st = 16; st > 0; st >>= 1) s += __shfl_xor_sync(0xffffffffu, s, st);
    if (lane == 0) red[warp] = s;
    __syncthreads();
    if (warp == 0) {
        float ss = red[lane & 7];
        #pragma unroll
        for (int st = 4; st > 0; st >>= 1) ss += __shfl_xor_sync(0xffffffffu, ss, st);
        if (lane == 0) red[0] = ss;
    }
    __syncthreads();
    const float inv = 1.f / red[0];

    v0.x *= inv; v0.y *= inv; v0.z *= inv; v0.w *= inv;
    v1.x *= inv; v1.y *= inv; v1.z *= inv; v1.w *= inv;
    p4[tid] = v0;
    p4[tid + 256] = v1;
}

// ---------------------------------------------------------------------------
// out = LayerNorm(X + R) * g + b, row length ED, one block per row.
// ---------------------------------------------------------------------------
__global__ __launch_bounds__(256) void add_ln_kernel(
    const float* __restrict__ X, const float* __restrict__ R,
    const float* __restrict__ g, const float* __restrict__ b,
    float* __restrict__ out)
{
    const long row = blockIdx.x;
    const float* x = X + row * ED;
    const float* r = R + row * ED;
    float* o = out + row * ED;
    const int t = threadIdx.x;

    float v[4];
    float s = 0.f, s2 = 0.f;
    #pragma unroll
    for (int i = 0; i < 4; i++) {
        float h = x[t + i * 256] + r[t + i * 256];
        v[i] = h;
        s += h;
        s2 += h * h;
    }
    __shared__ float rs[256], rq[256];
    rs[t] = s; rq[t] = s2; __syncthreads();
    for (int st = 128; st > 0; st >>= 1) {
        if (t < st) { rs[t] += rs[t + st]; rq[t] += rq[t + st]; }
        __syncthreads();
    }
    const float mean = rs[0] * (1.f / ED);
    const float var  = rq[0] * (1.f / ED) - mean * mean;
    const float inv  = rsqrtf(var + 1e-5f);
    #pragma unroll
    for (int i = 0; i < 4; i++) {
        int c = t + i * 256;
        o[c] = (v[i] - mean) * inv * g[c] + b[c];
    }
}

// ---------------------------------------------------------------------------
extern "C" void kernel_launch(void* const* d_in, const int* in_sizes, int n_in,
                              void* d_out, int out_size)
{
    const float* x   = (const float*)d_in[0];
    const float* Wq  = (const float*)d_in[1];
    const float* bq  = (const float*)d_in[2];
    const float* Wk  = (const float*)d_in[3];
    const float* bk  = (const float*)d_in[4];
    const float* Wv  = (const float*)d_in[5];
    const float* bv  = (const float*)d_in[6];
    const float* W1  = (const float*)d_in[7];
    const float* b1  = (const float*)d_in[8];
    const float* g1  = (const float*)d_in[9];
    const float* be1 = (const float*)d_in[10];
    const float* W2  = (const float*)d_in[11];
    const float* b2  = (const float*)d_in[12];
    const float* g2  = (const float*)d_in[13];
    const float* be2 = (const float*)d_in[14];
    float* out = (float*)d_out;

    float *q, *k, *v, *sc, *hd, *proj, *y, *tp;
    cudaGetSymbolAddress((void**)&q,    g_q);
    cudaGetSymbolAddress((void**)&k,    g_k);
    cudaGetSymbolAddress((void**)&v,    g_v);
    cudaGetSymbolAddress((void**)&sc,   g_scores);
    cudaGetSymbolAddress((void**)&hd,   g_heads);
    cudaGetSymbolAddress((void**)&proj, g_proj);
    cudaGetSymbolAddress((void**)&y,    g_y);
    cudaGetSymbolAddress((void**)&tp,   g_t);

    cudaFuncSetAttribute(gemm_tf32_kernel<false>,
                         cudaFuncAttributeMaxDynamicSharedMemorySize, SMEM_BYTES);
    cudaFuncSetAttribute(gemm_tf32_kernel<true>,
                         cudaFuncAttributeMaxDynamicSharedMemorySize, SMEM_BYTES);

    const float scale = 1.0f / 32.0f;   // 1/sqrt(1024)
    const long  hstride = (long)NB * SL * ED;
    dim3 blk(256);

    // ---- per-head Q/K/V projections (batched over H); bias offset h*ED
    {
        dim3 grid(ED / 256, MT / 128, NH);
        gemm_tf32_kernel<false><<<grid, blk, SMEM_BYTES>>>(x, Wq, bq, q, MT, ED, ED,
                                               0L, (long)ED * ED, hstride, (long)ED, 1.f, 0);
        gemm_tf32_kernel<false><<<grid, blk, SMEM_BYTES>>>(x, Wk, bk, k, MT, ED, ED,
                                               0L, (long)ED * ED, hstride, (long)ED, 1.f, 0);
        gemm_tf32_kernel<false><<<grid, blk, SMEM_BYTES>>>(x, Wv, bv, v, MT, ED, ED,
                                               0L, (long)ED * ED, hstride, (long)ED, 1.f, 0);
    }

    // ---- scores = scale * q @ k^T  (batched over H*B = 16)
    {
        dim3 grid(SL / 256, SL / 128, NH * NB);
        gemm_tf32_kernel<true><<<grid, blk, SMEM_BYTES>>>(q, k, nullptr, sc, SL, SL, ED,
                                              (long)SL * ED, (long)SL * ED, (long)SL * SL, 0L,
                                              scale, 0);
    }

    // ---- row softmax
    softmax_kernel<<<NH * NB * SL, 256>>>(sc);

    // ---- heads = attn @ v
    {
        dim3 grid(ED / 256, SL / 128, NH * NB);
        gemm_tf32_kernel<false><<<grid, blk, SMEM_BYTES>>>(sc, v, nullptr, hd, SL, ED, SL,
                                               (long)SL * SL, (long)SL * ED, (long)SL * ED, 0L,
                                               1.f, 0);
    }

    // ---- proj = concat(heads) @ W1 + b1 == sum_h heads[h] @ W1[h*D:(h+1)*D,:]
    for (int h = 0; h < NH; h++) {
        dim3 grid(ED / 256, MT / 128, 1);
        gemm_tf32_kernel<false><<<grid, blk, SMEM_BYTES>>>(hd + (long)h * hstride,
                                               W1 + (long)h * ED * ED,
                                               (h == 0) ? b1 : nullptr, proj,
                                               MT, ED, ED, 0L, 0L, 0L, 0L,
                                               1.f, (h > 0) ? 1 : 0);
    }

    // ---- y = LN(x + proj)
    add_ln_kernel<<<MT, 256>>>(x, proj, g1, be1, y);

    // ---- t = y @ W2 + b2
    {
        dim3 grid(ED / 256, MT / 128, 1);
        gemm_tf32_kernel<false><<<grid, blk, SMEM_BYTES>>>(y, W2, b2, tp, MT, ED, ED,
                                               0L, 0L, 0L, 0L, 1.f, 0);
    }

    // ---- out = LN(y + t)
    add_ln_kernel<<<MT, 256>>>(y, tp, g2, be2, out);
}